// round 12
// baseline (speedup 1.0000x reference)
#include <cuda_runtime.h>
#include <cuda_fp16.h>
#include <math.h>
#include <stdint.h>

// Problem constants
#define Bn 2
#define Tn 32
#define Nn 64
#define FINn 64
#define FOUTn 64
#define EDIMn 16
#define BT (Bn*Tn)            // 64
#define ROWS (BT*Nn)          // 4096
#define NBLK 512              // all CTAs co-resident: 4/SM * 148 = 592 >= 512

// -------- device scratch --------
__device__ __half g_xnh[ROWS*FINn];        // xn hi  [bt*64+j][f]
__device__ __half g_xnl[ROWS*FINn];        // xn lo
__device__ __half g_h[Bn*EDIMn*Nn*Nn];     // h fp16 [b][e][i][j]
__device__ __half g_w2[EDIMn*FINn*FOUTn];  // ew2 fp16 [e][f][o]
__device__ __half g_nw[FINn*FOUTn];        // nw fp16 [f][o]
__device__ float g_part[8][BT*Nn*FOUTn];   // per-eg partials (node-lin in eg0)
__device__ float g_T2[BT*FOUTn];           // eb2 contribution
__device__ unsigned g_bcnt;                // global barrier counter (ends at 0)
__device__ unsigned g_btcnt[BT];           // per-bt completion counters (end at 0)

__device__ __forceinline__ float gelu_exact(float v) {
    return 0.5f * v * (1.0f + erff(v * 0.70710678118654752f));
}
__device__ __forceinline__ void split_f16(float v, __half& h, __half& l) {
    h = __float2half_rn(v);
    l = __float2half_rn(v - __half2float(h));
}
__device__ __forceinline__ uint32_t pack_f16(__half a, __half b) {
    return ((uint32_t)__half_as_ushort(b) << 16) | (uint32_t)__half_as_ushort(a);
}
__device__ __forceinline__ uint32_t smem_u32(const void* p) {
    uint32_t a;
    asm("{ .reg .u64 t; cvta.to.shared.u64 t, %1; cvt.u32.u64 %0, t; }" : "=r"(a) : "l"(p));
    return a;
}

#define LDM_X4(r0,r1,r2,r3,addr) \
    asm volatile("ldmatrix.sync.aligned.m8n8.x4.shared.b16 {%0,%1,%2,%3}, [%4];" \
        : "=r"(r0),"=r"(r1),"=r"(r2),"=r"(r3) : "r"(addr))
#define LDM_X4T(r0,r1,r2,r3,addr) \
    asm volatile("ldmatrix.sync.aligned.m8n8.x4.trans.shared.b16 {%0,%1,%2,%3}, [%4];" \
        : "=r"(r0),"=r"(r1),"=r"(r2),"=r"(r3) : "r"(addr))

__device__ __forceinline__ void mma_f16(float* c, const uint32_t* a, uint32_t b0, uint32_t b1) {
    asm volatile("mma.sync.aligned.m16n8k16.row.col.f32.f16.f16.f32 "
        "{%0,%1,%2,%3}, {%4,%5,%6,%7}, {%8,%9}, {%0,%1,%2,%3};"
        : "+f"(c[0]), "+f"(c[1]), "+f"(c[2]), "+f"(c[3])
        : "r"(a[0]), "r"(a[1]), "r"(a[2]), "r"(a[3]), "r"(b0), "r"(b1));
}

#define CP_ASYNC16(saddr, gptr) \
    asm volatile("cp.async.cg.shared.global [%0], [%1], 16;" \
        :: "r"(saddr), "l"(__cvta_generic_to_global(gptr)) : "memory")
#define CP_COMMIT() asm volatile("cp.async.commit_group;" ::: "memory")
#define CP_WAIT0()  asm volatile("cp.async.wait_group 0;" ::: "memory")

// Single global barrier: atomicInc wrapping at NBLK-1 -> last arrival sets 0.
__device__ __forceinline__ void gbar() {
    __syncthreads();
    if (threadIdx.x == 0) {
        __threadfence();
        atomicInc(&g_bcnt, NBLK - 1u);
        volatile unsigned* p = &g_bcnt;
        while (*p != 0u) {}
        __threadfence();
    }
    __syncthreads();
}

#define LDA 72
#define TILE (64*LDA)           // 4608 halves = 9216 B
#define FUS_SMEM (6*TILE*2)     // 55296 B -> 4 CTAs/SM

__global__ void __launch_bounds__(128, 4)
k_all(const float* __restrict__ x,   const float* __restrict__ adj,
      const float* __restrict__ ew1, const float* __restrict__ eb1,
      const float* __restrict__ ew2, const float* __restrict__ eb2,
      const float* __restrict__ nw,  const float* __restrict__ nb,
      const float* __restrict__ gw,  const float* __restrict__ gb,
      const float* __restrict__ gms, float* __restrict__ out) {
    extern __shared__ __align__(16) __half ds[];
    __shared__ unsigned s_old;
    int tid = threadIdx.x, blk = blockIdx.x;

    // =================== PHASE A: prologue ===================
    if (blk < BT) {
        // ---- norm + T2 for bt = blk (128 thr: 2 groups x 64 features) ----
        int bt = blk;
        int f = tid & 63;
        int g = tid >> 6;                       // 0..1, 32 rows each
        float* sA   = (float*)ds;               // [2][64]
        float* sB   = sA + 128;
        float* sMul = sB + 128;
        float* sSub = sMul + 64;
        float* sAdd = sSub + 64;
        float* sSf  = sAdd + 64;

        const float* xp = x + bt * (Nn * FINn) + f;
        float s = 0.f, ss = 0.f;
#pragma unroll
        for (int n = g * 32; n < g * 32 + 32; n++) {
            float v = xp[n * FINn];
            s += v; ss += v * v;
        }
        sA[g * 64 + f] = s; sB[g * 64 + f] = ss;
        __syncthreads();

        if (g == 0) {
            float st  = sA[f] + sA[64 + f];
            float sst = sB[f] + sB[64 + f];
            float mean = st * (1.0f / Nn);
            float var  = sst * (1.0f / Nn) - mean * mean;
            float rstd = rsqrtf(var + 1e-5f);
            float w = gw[f], bbv = gb[f];
            float sub = mean * gms[0];
            sMul[f] = rstd * w;
            sSub[f] = sub;
            sAdd[f] = bbv;
            sSf[f]  = (float)Nn * ((mean - sub) * rstd * w + bbv);
        }
        __syncthreads();

        float mul = sMul[f], sub = sSub[f], add = sAdd[f];
#pragma unroll
        for (int n = g * 32; n < g * 32 + 32; n++) {
            float v = (xp[n * FINn] - sub) * mul + add;
            __half h, l; split_f16(v, h, l);
            g_xnh[bt * 4096 + n * 64 + f] = h;
            g_xnl[bt * 4096 + n * 64 + f] = l;
        }

        int o = f;
        float acc = 0.f;
#pragma unroll
        for (int ff = g * 32; ff < g * 32 + 32; ff++)
            acc += sSf[ff] * eb2[ff * FOUTn + o];
        __syncthreads();
        sA[g * 64 + o] = acc;
        __syncthreads();
        if (g == 0)
            g_T2[bt * FOUTn + o] = sA[o] + sA[64 + o];
        __syncthreads();
    } else if (blk < BT + 32) {
        // nw convert: 4096 elems over blocks 64..95
        int idx = (blk - BT) * 128 + tid;
        g_nw[idx] = __float2half_rn(nw[idx]);
    }

    // edge (all blocks): 131072 elems, 2/thread, fp16
    {
        int idx2 = blk * 256 + tid * 2;
        int row = idx2 >> 6;                    // (b,e,i)
        int j = idx2 & 63;
        int b = row >> 10, e = (row >> 6) & 15, i = row & 63;
        float2 a2 = *(const float2*)(adj + b * 4096 + i * 64 + j);
        float w1 = ew1[e], b1 = eb1[e];
        __half h0 = __float2half_rn(gelu_exact(a2.x * w1 + b1));
        __half h1 = __float2half_rn(gelu_exact(a2.y * w1 + b1));
        *(uint32_t*)(g_h + idx2) = pack_f16(h0, h1);
    }
    // ew2 convert (all blocks): 65536 elems, 1/thread
    {
        int idx = blk * 128 + tid;
        g_w2[idx] = __float2half_rn(ew2[idx]);
    }

    gbar();

    // =================== PHASE B: fused GEMM (2 e per block) + finisher ===================
    {
        __half *P0 = ds, *P1 = ds + TILE;       // X tiles, recycled as P after frags
        __half *W0 = ds + 2*TILE, *W1 = ds + 3*TILE;
        __half *H0 = ds + 4*TILE, *H1 = ds + 5*TILE;

        int warp = tid >> 5, lane = tid & 31;
        int bt = blk >> 3, eg = blk & 7;
        int b = bt >> 5;
        int ebase = eg * 2;

        // prefetch all 6 tiles (X hi/lo, W e0/e1, H e0/e1)
        {
            const __half* xhp = g_xnh + bt * 4096;
            const __half* xlp = g_xnl + bt * 4096;
            const __half* wp0 = g_w2 + ebase * 4096;
            const __half* wp1 = g_w2 + (ebase + 1) * 4096;
            const __half* hp0 = g_h + (b * 16 + ebase) * 4096;
            const __half* hp1 = g_h + (b * 16 + ebase + 1) * 4096;
            uint32_t sXh = smem_u32(P0), sXl = smem_u32(P1);
            uint32_t sW0 = smem_u32(W0), sW1 = smem_u32(W1);
            uint32_t sH0 = smem_u32(H0), sH1 = smem_u32(H1);
#pragma unroll
            for (int l = 0; l < 4; l++) {
                int idx = tid + l * 128;        // 512 uint4 per tile
                int r = idx >> 3, q = idx & 7;
                uint32_t off = (uint32_t)(r * LDA + q * 8) * 2;
                int src = r * 64 + q * 8;
                CP_ASYNC16(sXh + off, xhp + src);
                CP_ASYNC16(sXl + off, xlp + src);
                CP_ASYNC16(sW0 + off, wp0 + src);
                CP_ASYNC16(sW1 + off, wp1 + src);
                CP_ASYNC16(sH0 + off, hp0 + src);
                CP_ASYNC16(sH1 + off, hp1 + src);
            }
            CP_COMMIT();
        }
        CP_WAIT0();
        __syncthreads();

        uint32_t xBh = smem_u32(P0), xBl = smem_u32(P1);
        int g = lane >> 3, lr = lane & 7;
        int arow = warp * 16 + (g & 1) * 8 + lr;
        int acol0 = (g >> 1) * 8;

        // persistent xn A-fragments; X tiles then become P0/P1
        uint32_t xh[16], xl[16];
#pragma unroll
        for (int ks = 0; ks < 4; ks++) {
            uint32_t off = (uint32_t)(arow * LDA + ks * 16 + acol0) * 2;
            LDM_X4(xh[4*ks], xh[4*ks+1], xh[4*ks+2], xh[4*ks+3], xBh + off);
            LDM_X4(xl[4*ks], xl[4*ks+1], xl[4*ks+2], xl[4*ks+3], xBl + off);
        }
        __syncthreads();            // all warps done reading X tiles

        int cr = lane >> 2, cc2 = (lane & 3) * 2;

        // ---- stage 0: mma1 both e -> P0/P1 ----
#pragma unroll
        for (int e2 = 0; e2 < 2; e2++) {
            uint32_t wB = smem_u32(e2 ? W1 : W0);
            __half* Pt = e2 ? P1 : P0;
#pragma unroll
            for (int nt = 0; nt < 8; nt++) {
                float p[4] = {0.f,0.f,0.f,0.f};
                uint32_t bw[8];
                uint32_t off1 = (uint32_t)((g * 8 + lr) * LDA + nt * 8) * 2;
                uint32_t off2 = (uint32_t)((32 + g * 8 + lr) * LDA + nt * 8) * 2;
                LDM_X4T(bw[0], bw[1], bw[2], bw[3], wB + off1);
                LDM_X4T(bw[4], bw[5], bw[6], bw[7], wB + off2);
#pragma unroll
                for (int ks = 0; ks < 4; ks++) {
                    mma_f16(p, xh + 4*ks, bw[2*ks], bw[2*ks+1]);
                    mma_f16(p, xl + 4*ks, bw[2*ks], bw[2*ks+1]);
                }
#pragma unroll
                for (int half = 0; half < 2; half++) {
                    int row = warp * 16 + cr + half * 8;
                    int col = nt * 8 + cc2;
                    *(uint32_t*)(Pt + row * LDA + col) =
                        pack_f16(__float2half_rn(p[half*2]), __float2half_rn(p[half*2+1]));
                }
            }
        }
        __syncthreads();

        // ---- stage 1: mma2 both e: agg += h(e) @ P(e) ----
        float agg[8][4];
#pragma unroll
        for (int i = 0; i < 8; i++) { agg[i][0]=0.f; agg[i][1]=0.f; agg[i][2]=0.f; agg[i][3]=0.f; }

#pragma unroll
        for (int e2 = 0; e2 < 2; e2++) {
            uint32_t hB = smem_u32(e2 ? H1 : H0);
            uint32_t pB = smem_u32(e2 ? P1 : P0);
            uint32_t ahh[16];
#pragma unroll
            for (int ks = 0; ks < 4; ks++) {
                uint32_t off = (uint32_t)(arow * LDA + ks * 16 + acol0) * 2;
                LDM_X4(ahh[4*ks], ahh[4*ks+1], ahh[4*ks+2], ahh[4*ks+3], hB + off);
            }
#pragma unroll
            for (int kh = 0; kh < 2; kh++) {
#pragma unroll
                for (int nt = 0; nt < 8; nt++) {
                    uint32_t bp[4];
                    uint32_t off = (uint32_t)((kh * 32 + g * 8 + lr) * LDA + nt * 8) * 2;
                    LDM_X4T(bp[0], bp[1], bp[2], bp[3], pB + off);
#pragma unroll
                    for (int k2 = 0; k2 < 2; k2++) {
                        int ks = kh * 2 + k2;
                        mma_f16(agg[nt], ahh + 4*ks, bp[2*k2], bp[2*k2+1]);
                    }
                }
            }
        }

        // ---- eg 0: node-lin  agg += (Xh+Xl) @ nw  (x frags still in regs) ----
        if (eg == 0) {
            __syncthreads();        // P0/P1 reads done before W0 overwrite? (W0 free; just order)
#pragma unroll
            for (int l = 0; l < 4; l++) {
                int idx = tid + l * 128;
                int r = idx >> 3, q = idx & 7;
                *(uint4*)(W0 + r * LDA + q * 8) = *(const uint4*)(g_nw + r * 64 + q * 8);
            }
            __syncthreads();
            uint32_t wB = smem_u32(W0);
#pragma unroll
            for (int kh = 0; kh < 2; kh++) {
#pragma unroll
                for (int nt = 0; nt < 8; nt++) {
                    uint32_t bw[4];
                    uint32_t off = (uint32_t)((kh * 32 + g * 8 + lr) * LDA + nt * 8) * 2;
                    LDM_X4T(bw[0], bw[1], bw[2], bw[3], wB + off);
#pragma unroll
                    for (int k2 = 0; k2 < 2; k2++) {
                        int ks = kh * 2 + k2;
                        mma_f16(agg[nt], xh + 4*ks, bw[2*k2], bw[2*k2+1]);
                        mma_f16(agg[nt], xl + 4*ks, bw[2*k2], bw[2*k2+1]);
                    }
                }
            }
        }

        // ---- store partial ----
        float* Cdst = g_part[eg] + bt * (Nn * FOUTn);
#pragma unroll
        for (int nt = 0; nt < 8; nt++) {
            int col = nt * 8 + cc2;
            *(float2*)(Cdst + (warp * 16 + cr) * FOUTn + col)     = make_float2(agg[nt][0], agg[nt][1]);
            *(float2*)(Cdst + (warp * 16 + cr + 8) * FOUTn + col) = make_float2(agg[nt][2], agg[nt][3]);
        }

        // ---- per-bt finisher: last of 8 eg-blocks sums + gelu + out ----
        __threadfence();
        __syncthreads();
        if (tid == 0) s_old = atomicAdd(&g_btcnt[bt], 1u);
        __syncthreads();
        if (s_old == 7u) {
            __threadfence();
            int base = bt * (Nn * FOUTn);
#pragma unroll
            for (int l = 0; l < 8; l++) {
                int idx = tid + l * 128;          // 1024 float4 tasks for this bt
                int e0 = base + idx * 4;
                int o  = (idx * 4) & 63;
                float4 p0 = *(const float4*)(g_part[0] + e0);
                float4 p1 = *(const float4*)(g_part[1] + e0);
                float4 p2 = *(const float4*)(g_part[2] + e0);
                float4 p3 = *(const float4*)(g_part[3] + e0);
                float4 p4 = *(const float4*)(g_part[4] + e0);
                float4 p5 = *(const float4*)(g_part[5] + e0);
                float4 p6 = *(const float4*)(g_part[6] + e0);
                float4 p7 = *(const float4*)(g_part[7] + e0);
                float4 nbv = *(const float4*)(nb + o);
                float4 t2v = *(const float4*)(g_T2 + bt * FOUTn + o);
                float v0 = ((p0.x + p1.x) + (p2.x + p3.x)) + ((p4.x + p5.x) + (p6.x + p7.x)) + nbv.x + t2v.x;
                float v1 = ((p0.y + p1.y) + (p2.y + p3.y)) + ((p4.y + p5.y) + (p6.y + p7.y)) + nbv.y + t2v.y;
                float v2 = ((p0.z + p1.z) + (p2.z + p3.z)) + ((p4.z + p5.z) + (p6.z + p7.z)) + nbv.z + t2v.z;
                float v3 = ((p0.w + p1.w) + (p2.w + p3.w)) + ((p4.w + p5.w) + (p6.w + p7.w)) + nbv.w + t2v.w;
                *(float4*)(out + e0) = make_float4(gelu_exact(v0), gelu_exact(v1),
                                                   gelu_exact(v2), gelu_exact(v3));
            }
            if (tid == 0) g_btcnt[bt] = 0;        // reset for next graph replay
        }
    }
}

extern "C" void kernel_launch(void* const* d_in, const int* in_sizes, int n_in,
                              void* d_out, int out_size) {
    const float* x   = (const float*)d_in[0];
    const float* adj = (const float*)d_in[1];
    const float* ew1 = (const float*)d_in[2];
    const float* eb1 = (const float*)d_in[3];
    const float* ew2 = (const float*)d_in[4];
    const float* eb2 = (const float*)d_in[5];
    const float* nw  = (const float*)d_in[6];
    const float* nb  = (const float*)d_in[7];
    const float* gw  = (const float*)d_in[8];
    const float* gb  = (const float*)d_in[9];
    const float* gms = (const float*)d_in[10];
    float* out = (float*)d_out;

    cudaFuncSetAttribute(k_all, cudaFuncAttributeMaxDynamicSharedMemorySize, FUS_SMEM);
    k_all<<<NBLK, 128, FUS_SMEM>>>(x, adj, ew1, eb1, ew2, eb2, nw, nb, gw, gb, gms, out);
}

// round 13
// speedup vs baseline: 1.1913x; 1.1913x over previous
#include <cuda_runtime.h>
#include <cuda_fp16.h>
#include <math.h>
#include <stdint.h>

// Problem constants
#define Bn 2
#define Tn 32
#define Nn 64
#define FINn 64
#define FOUTn 64
#define EDIMn 16
#define BT (Bn*Tn)            // 64
#define ROWS (BT*Nn)          // 4096
#define NBLK 256              // all CTAs co-resident: 2/SM * 148 = 296 >= 256

// -------- device scratch --------
__device__ __half g_h[Bn*EDIMn*Nn*Nn];     // h fp16 [b][e][i][j]
__device__ __half g_w2[EDIMn*FINn*FOUTn];  // ew2 fp16 [e][f][o]
__device__ __half g_nw[FINn*FOUTn];        // nw fp16 [f][o]
__device__ float g_red[BT*4*2*64];         // partial (s,ss): [bt][part][0/1][f]
__device__ float g_part[4][BT*Nn*FOUTn];   // per-eg partials (node-lin in eg0)
__device__ unsigned g_bcnt;                // global barrier counter (ends at 0)
__device__ unsigned g_btcnt[BT];           // per-bt completion counters (end at 0)

__device__ __forceinline__ float gelu_exact(float v) {
    return 0.5f * v * (1.0f + erff(v * 0.70710678118654752f));
}
__device__ __forceinline__ void split_f16(float v, __half& h, __half& l) {
    h = __float2half_rn(v);
    l = __float2half_rn(v - __half2float(h));
}
__device__ __forceinline__ uint32_t pack_f16(__half a, __half b) {
    return ((uint32_t)__half_as_ushort(b) << 16) | (uint32_t)__half_as_ushort(a);
}
__device__ __forceinline__ uint32_t smem_u32(const void* p) {
    uint32_t a;
    asm("{ .reg .u64 t; cvta.to.shared.u64 t, %1; cvt.u32.u64 %0, t; }" : "=r"(a) : "l"(p));
    return a;
}

#define LDM_X4(r0,r1,r2,r3,addr) \
    asm volatile("ldmatrix.sync.aligned.m8n8.x4.shared.b16 {%0,%1,%2,%3}, [%4];" \
        : "=r"(r0),"=r"(r1),"=r"(r2),"=r"(r3) : "r"(addr))
#define LDM_X4T(r0,r1,r2,r3,addr) \
    asm volatile("ldmatrix.sync.aligned.m8n8.x4.trans.shared.b16 {%0,%1,%2,%3}, [%4];" \
        : "=r"(r0),"=r"(r1),"=r"(r2),"=r"(r3) : "r"(addr))

__device__ __forceinline__ void mma_f16(float* c, const uint32_t* a, uint32_t b0, uint32_t b1) {
    asm volatile("mma.sync.aligned.m16n8k16.row.col.f32.f16.f16.f32 "
        "{%0,%1,%2,%3}, {%4,%5,%6,%7}, {%8,%9}, {%0,%1,%2,%3};"
        : "+f"(c[0]), "+f"(c[1]), "+f"(c[2]), "+f"(c[3])
        : "r"(a[0]), "r"(a[1]), "r"(a[2]), "r"(a[3]), "r"(b0), "r"(b1));
}

#define CP_ASYNC16(saddr, gptr) \
    asm volatile("cp.async.cg.shared.global [%0], [%1], 16;" \
        :: "r"(saddr), "l"(__cvta_generic_to_global(gptr)) : "memory")
#define CP_COMMIT() asm volatile("cp.async.commit_group;" ::: "memory")
#define CP_WAIT0()  asm volatile("cp.async.wait_group 0;" ::: "memory")

// Single global barrier: atomicInc wrapping at NBLK-1 -> last arrival sets 0.
__device__ __forceinline__ void gbar() {
    __syncthreads();
    if (threadIdx.x == 0) {
        __threadfence();
        atomicInc(&g_bcnt, NBLK - 1u);
        volatile unsigned* p = &g_bcnt;
        while (*p != 0u) {}
        __threadfence();
    }
    __syncthreads();
}

#define LDA 72
#define TILE (64*LDA)           // 4608 halves
#define FUS_SMEM (10*TILE*2)    // 92160 B -> 2 CTAs/SM

__global__ void __launch_bounds__(256, 2)
k_all(const float* __restrict__ x,   const float* __restrict__ adj,
      const float* __restrict__ ew1, const float* __restrict__ eb1,
      const float* __restrict__ ew2, const float* __restrict__ eb2,
      const float* __restrict__ nw,  const float* __restrict__ nb,
      const float* __restrict__ gw,  const float* __restrict__ gb,
      const float* __restrict__ gms, float* __restrict__ out) {
    extern __shared__ __align__(16) __half ds[];
    __shared__ float redA[256], redB[256];
    __shared__ float sMul[64], sSub[64], sAdd[64], sS[64];
    __shared__ unsigned s_old;
    int tid = threadIdx.x, blk = blockIdx.x;
    int bt = blk >> 2, eg = blk & 3;
    int b = bt >> 5;

    // =================== PHASE A: uniform prologue ===================
    {   // partial norm stats: this block covers rows part*16..+15 of x[bt]
        int part = eg;
        int f = tid & 63, sub = tid >> 6;       // 4 subs x 4 rows
        const float* xp = x + bt * 4096 + (part * 16 + sub * 4) * 64 + f;
        float s = 0.f, ss = 0.f;
#pragma unroll
        for (int r = 0; r < 4; r++) { float v = xp[r * 64]; s += v; ss += v * v; }
        redA[sub * 64 + f] = s; redB[sub * 64 + f] = ss;
        __syncthreads();
        if (sub == 0) {
            float st  = redA[f] + redA[64 + f] + redA[128 + f] + redA[192 + f];
            float sst = redB[f] + redB[64 + f] + redB[128 + f] + redB[192 + f];
            *(float2*)(g_red + ((bt * 4 + part) * 64 + f) * 2) = make_float2(st, sst);
        }
    }
    if (blk >= 64 && blk < 80) {                // nw convert: 4096 elems
        int idx = (blk - 64) * 256 + tid;
        g_nw[idx] = __float2half_rn(nw[idx]);
    }
    {   // edge: 131072 elems, 2/thread, fp16
        int idx2 = blk * 512 + tid * 2;
        int row = idx2 >> 6;                    // (b,e,i)
        int j = idx2 & 63;
        int be = row >> 10, e = (row >> 6) & 15, i = row & 63;
        float2 a2 = *(const float2*)(adj + be * 4096 + i * 64 + j);
        float w1 = ew1[e], b1 = eb1[e];
        __half h0 = __float2half_rn(gelu_exact(a2.x * w1 + b1));
        __half h1 = __float2half_rn(gelu_exact(a2.y * w1 + b1));
        *(uint32_t*)(g_h + idx2) = pack_f16(h0, h1);
    }
    {   // ew2 convert: 65536 elems, 1/thread
        int idx = blk * 256 + tid;
        g_w2[idx] = __float2half_rn(ew2[idx]);
    }

    gbar();

    // =================== PHASE B: norm-in-smem + fused GEMM + finisher ===================
    {
        __half *Xh = ds, *Xl = ds + TILE;       // recycled as P0/P1 after frags
        __half *P0 = Xh, *P1 = Xl;
        __half *Wt[2][2] = {{ds + 2*TILE, ds + 3*TILE}, {ds + 4*TILE, ds + 5*TILE}};
        __half *Ht[2][2] = {{ds + 6*TILE, ds + 7*TILE}, {ds + 8*TILE, ds + 9*TILE}};
        float* xs = (float*)(ds + 4*TILE);      // fp32 x stage overlays Wt[1] (18KB>=16KB)

        int warp = tid >> 5, lane = tid & 31;
        int wr = warp >> 1, wc = warp & 1;

        // prefetch: x[bt] fp32 + pair 0 (W/H for e0, e1)
        {
            const float* xp = x + bt * 4096;
            uint32_t sXs = smem_u32(xs);
#pragma unroll
            for (int l = 0; l < 4; l++) {
                int idx = tid + l * 256;        // 1024 uint4
                CP_ASYNC16(sXs + idx * 16, xp + idx * 4);
            }
#pragma unroll
            for (int e2 = 0; e2 < 2; e2++) {
                int e = eg * 4 + e2;
                uint32_t sW = smem_u32(Wt[0][e2]), sH = smem_u32(Ht[0][e2]);
                const __half* wp = g_w2 + e * 4096;
                const __half* hp = g_h + (b * 16 + e) * 4096;
#pragma unroll
                for (int l = 0; l < 2; l++) {
                    int idx = tid + l * 256;
                    int r = idx >> 3, q = idx & 7;
                    uint32_t off = (uint32_t)(r * LDA + q * 8) * 2;
                    CP_ASYNC16(sW + off, wp + r * 64 + q * 8);
                    CP_ASYNC16(sH + off, hp + r * 64 + q * 8);
                }
            }
            CP_COMMIT();
        }

        // fold stats while cp.async is in flight (threads 0..63)
        if (tid < 64) {
            int f = tid;
            float2 p0 = *(const float2*)(g_red + ((bt * 4 + 0) * 64 + f) * 2);
            float2 p1 = *(const float2*)(g_red + ((bt * 4 + 1) * 64 + f) * 2);
            float2 p2 = *(const float2*)(g_red + ((bt * 4 + 2) * 64 + f) * 2);
            float2 p3 = *(const float2*)(g_red + ((bt * 4 + 3) * 64 + f) * 2);
            float st  = (p0.x + p1.x) + (p2.x + p3.x);
            float sst = (p0.y + p1.y) + (p2.y + p3.y);
            float mean = st * (1.0f / Nn);
            float var  = sst * (1.0f / Nn) - mean * mean;
            float rstd = rsqrtf(var + 1e-5f);
            float w = gw[f], bbv = gb[f];
            float sub = mean * gms[0];
            sMul[f] = rstd * w;
            sSub[f] = sub;
            sAdd[f] = bbv;
            sS[f]   = (float)Nn * ((mean - sub) * rstd * w + bbv);
        }
        CP_WAIT0();
        __syncthreads();

        // normalize + split into Xh/Xl (16 elems/thread)
#pragma unroll
        for (int l = 0; l < 16; l++) {
            int idx = tid + l * 256;            // 4096 elems
            int r = idx >> 6, f2 = idx & 63;
            float v = (xs[idx] - sSub[f2]) * sMul[f2] + sAdd[f2];
            __half h, lo; split_f16(v, h, lo);
            Xh[r * LDA + f2] = h;
            Xl[r * LDA + f2] = lo;
        }
        __syncthreads();

        uint32_t xBh = smem_u32(Xh), xBl = smem_u32(Xl);
        int g = lane >> 3, lr = lane & 7;
        int arow = wr * 16 + (g & 1) * 8 + lr;
        int acol0 = (g >> 1) * 8;

        // persistent xn A-fragments; X tiles then become P0/P1
        uint32_t xh[16], xl[16];
#pragma unroll
        for (int ks = 0; ks < 4; ks++) {
            uint32_t off = (uint32_t)(arow * LDA + ks * 16 + acol0) * 2;
            LDM_X4(xh[4*ks], xh[4*ks+1], xh[4*ks+2], xh[4*ks+3], xBh + off);
            LDM_X4(xl[4*ks], xl[4*ks+1], xl[4*ks+2], xl[4*ks+3], xBl + off);
        }
        __syncthreads();            // all warps done reading X tiles; xs dead

        // prefetch pair 1 (e2, e3) into Wt[1]/Ht[1] (overwrites xs region)
        {
#pragma unroll
            for (int e2 = 0; e2 < 2; e2++) {
                int e = eg * 4 + 2 + e2;
                uint32_t sW = smem_u32(Wt[1][e2]), sH = smem_u32(Ht[1][e2]);
                const __half* wp = g_w2 + e * 4096;
                const __half* hp = g_h + (b * 16 + e) * 4096;
#pragma unroll
                for (int l = 0; l < 2; l++) {
                    int idx = tid + l * 256;
                    int r = idx >> 3, q = idx & 7;
                    uint32_t off = (uint32_t)(r * LDA + q * 8) * 2;
                    CP_ASYNC16(sW + off, wp + r * 64 + q * 8);
                    CP_ASYNC16(sH + off, hp + r * 64 + q * 8);
                }
            }
            CP_COMMIT();
        }

        float agg[4][4];
#pragma unroll
        for (int i = 0; i < 4; i++) { agg[i][0]=0.f; agg[i][1]=0.f; agg[i][2]=0.f; agg[i][3]=0.f; }

        int cr = lane >> 2, cc2 = (lane & 3) * 2;
        uint32_t pB[2] = { smem_u32(P0), smem_u32(P1) };

        for (int pp = 0; pp < 2; pp++) {
            // ---- mma1 for both e of the pair: P(e2) = (Xh+Xl) @ W ----
#pragma unroll
            for (int e2 = 0; e2 < 2; e2++) {
                uint32_t wB = smem_u32(Wt[pp][e2]);
                __half* Pt = e2 ? P1 : P0;
#pragma unroll
                for (int nt = 0; nt < 4; nt++) {
                    float p[4] = {0.f,0.f,0.f,0.f};
                    uint32_t bw[8];
                    uint32_t off1 = (uint32_t)((g * 8 + lr) * LDA + wc * 32 + nt * 8) * 2;
                    uint32_t off2 = (uint32_t)((32 + g * 8 + lr) * LDA + wc * 32 + nt * 8) * 2;
                    LDM_X4T(bw[0], bw[1], bw[2], bw[3], wB + off1);
                    LDM_X4T(bw[4], bw[5], bw[6], bw[7], wB + off2);
#pragma unroll
                    for (int ks = 0; ks < 4; ks++) {
                        mma_f16(p, xh + 4*ks, bw[2*ks], bw[2*ks+1]);
                        mma_f16(p, xl + 4*ks, bw[2*ks], bw[2*ks+1]);
                    }
#pragma unroll
                    for (int half = 0; half < 2; half++) {
                        int row = wr * 16 + cr + half * 8;
                        int col = wc * 32 + nt * 8 + cc2;
                        *(uint32_t*)(Pt + row * LDA + col) =
                            pack_f16(__float2half_rn(p[half*2]), __float2half_rn(p[half*2+1]));
                    }
                }
            }
            if (pp == 0) CP_WAIT0();
            __syncthreads();

            // ---- mma2 for both e: agg += h(e) @ P(e) ----
#pragma unroll
            for (int e2 = 0; e2 < 2; e2++) {
                uint32_t hB = smem_u32(Ht[pp][e2]);
                uint32_t ahh[16];
#pragma unroll
                for (int ks = 0; ks < 4; ks++) {
                    uint32_t off = (uint32_t)(arow * LDA + ks * 16 + acol0) * 2;
                    LDM_X4(ahh[4*ks], ahh[4*ks+1], ahh[4*ks+2], ahh[4*ks+3], hB + off);
                }
#pragma unroll
                for (int kh = 0; kh < 2; kh++) {
#pragma unroll
                    for (int nt = 0; nt < 4; nt++) {
                        uint32_t bp[4];
                        uint32_t off = (uint32_t)((kh * 32 + g * 8 + lr) * LDA + wc * 32 + nt * 8) * 2;
                        LDM_X4T(bp[0], bp[1], bp[2], bp[3], pB[e2] + off);
#pragma unroll
                        for (int k2 = 0; k2 < 2; k2++) {
                            int ks = kh * 2 + k2;
                            mma_f16(agg[nt], ahh + 4*ks, bp[2*k2], bp[2*k2+1]);
                        }
                    }
                }
            }
            __syncthreads();
        }

        // ---- eg 0: node-lin  agg += (Xh+Xl) @ nw ----
        if (eg == 0) {
#pragma unroll
            for (int l = 0; l < 2; l++) {
                int idx = tid + l * 256;
                int r = idx >> 3, q = idx & 7;
                *(uint4*)(Wt[0][0] + r * LDA + q * 8) = *(const uint4*)(g_nw + r * 64 + q * 8);
            }
            __syncthreads();
            uint32_t wB = smem_u32(Wt[0][0]);
#pragma unroll
            for (int kh = 0; kh < 2; kh++) {
#pragma unroll
                for (int nt = 0; nt < 4; nt++) {
                    uint32_t bw[4];
                    uint32_t off = (uint32_t)((kh * 32 + g * 8 + lr) * LDA + wc * 32 + nt * 8) * 2;
                    LDM_X4T(bw[0], bw[1], bw[2], bw[3], wB + off);
#pragma unroll
                    for (int k2 = 0; k2 < 2; k2++) {
                        int ks = kh * 2 + k2;
                        mma_f16(agg[nt], xh + 4*ks, bw[2*k2], bw[2*k2+1]);
                        mma_f16(agg[nt], xl + 4*ks, bw[2*k2], bw[2*k2+1]);
                    }
                }
            }
        }

        // ---- store partial ----
        float* Cdst = g_part[eg] + bt * (Nn * FOUTn);
#pragma unroll
        for (int nt = 0; nt < 4; nt++) {
            int col = wc * 32 + nt * 8 + cc2;
            *(float2*)(Cdst + (wr * 16 + cr) * FOUTn + col)     = make_float2(agg[nt][0], agg[nt][1]);
            *(float2*)(Cdst + (wr * 16 + cr + 8) * FOUTn + col) = make_float2(agg[nt][2], agg[nt][3]);
        }

        // ---- per-bt finisher: last of 4 eg-blocks sums + T2 + gelu + out ----
        __threadfence();
        __syncthreads();
        if (tid == 0) s_old = atomicAdd(&g_btcnt[bt], 1u);
        __syncthreads();
        if (s_old == 3u) {
            __threadfence();
            // T2[o] = sum_f S[f]*eb2[f*64+o] via 4-group partials in redA
            {
                int o = tid & 63, g4 = tid >> 6;
                float acc = 0.f;
#pragma unroll
                for (int ff = g4 * 16; ff < g4 * 16 + 16; ff++)
                    acc += sS[ff] * eb2[ff * FOUTn + o];
                redA[g4 * 64 + o] = acc;
            }
            __syncthreads();
            int base = bt * (Nn * FOUTn);
#pragma unroll
            for (int l = 0; l < 4; l++) {
                int idx = tid + l * 256;          // 1024 float4 tasks for this bt
                int e0 = base + idx * 4;
                int o  = (idx * 4) & 63;
                float4 p0 = *(const float4*)(g_part[0] + e0);
                float4 p1 = *(const float4*)(g_part[1] + e0);
                float4 p2 = *(const float4*)(g_part[2] + e0);
                float4 p3 = *(const float4*)(g_part[3] + e0);
                float4 nbv = *(const float4*)(nb + o);
                float t20 = redA[o]   + redA[64+o]   + redA[128+o]   + redA[192+o];
                float t21 = redA[o+1] + redA[64+o+1] + redA[128+o+1] + redA[192+o+1];
                float t22 = redA[o+2] + redA[64+o+2] + redA[128+o+2] + redA[192+o+2];
                float t23 = redA[o+3] + redA[64+o+3] + redA[128+o+3] + redA[192+o+3];
                float v0 = p0.x + p1.x + p2.x + p3.x + nbv.x + t20;
                float v1 = p0.y + p1.y + p2.y + p3.y + nbv.y + t21;
                float v2 = p0.z + p1.z + p2.z + p3.z + nbv.z + t22;
                float v3 = p0.w + p1.w + p2.w + p3.w + nbv.w + t23;
                *(float4*)(out + e0) = make_float4(gelu_exact(v0), gelu_exact(v1),
                                                   gelu_exact(v2), gelu_exact(v3));
            }
            if (tid == 0) g_btcnt[bt] = 0;        // reset for next graph replay
        }
    }
}

extern "C" void kernel_launch(void* const* d_in, const int* in_sizes, int n_in,
                              void* d_out, int out_size) {
    const float* x   = (const float*)d_in[0];
    const float* adj = (const float*)d_in[1];
    const float* ew1 = (const float*)d_in[2];
    const float* eb1 = (const float*)d_in[3];
    const float* ew2 = (const float*)d_in[4];
    const float* eb2 = (const float*)d_in[5];
    const float* nw  = (const float*)d_in[6];
    const float* nb  = (const float*)d_in[7];
    const float* gw  = (const float*)d_in[8];
    const float* gb  = (const float*)d_in[9];
    const float* gms = (const float*)d_in[10];
    float* out = (float*)d_out;

    cudaFuncSetAttribute(k_all, cudaFuncAttributeMaxDynamicSharedMemorySize, FUS_SMEM);
    k_all<<<NBLK, 256, FUS_SMEM>>>(x, adj, ew1, eb1, ew2, eb2, nw, nb, gw, gb, gms, out);
}

// round 14
// speedup vs baseline: 1.3183x; 1.1067x over previous
#include <cuda_runtime.h>
#include <cuda_fp16.h>
#include <math.h>
#include <stdint.h>

// Problem constants
#define Bn 2
#define Tn 32
#define Nn 64
#define FINn 64
#define FOUTn 64
#define EDIMn 16
#define BT (Bn*Tn)            // 64
#define ROWS (BT*Nn)          // 4096
#define NBLK 256              // all CTAs co-resident: 2/SM * 148 = 296 >= 256

// -------- device scratch --------
__device__ __half g_xnh[ROWS*FINn];        // xn hi  [bt*64+j][f]
__device__ __half g_xnl[ROWS*FINn];        // xn lo
__device__ __half g_h[Bn*EDIMn*Nn*Nn];     // h fp16 [b][e][i][j]
__device__ __half g_w2[EDIMn*FINn*FOUTn];  // ew2 fp16 [e][f][o]
__device__ __half g_nw[FINn*FOUTn];        // nw fp16 [f][o]
__device__ float g_part[4][BT*Nn*FOUTn];   // per-eg partials (node-lin quartered)
__device__ float g_T2[BT*FOUTn];           // eb2 contribution
__device__ unsigned g_bcnt;                // global barrier counter (ends at 0)
__device__ unsigned g_btcnt[BT];           // per-bt barrier counters (end at 0)

__device__ __forceinline__ float gelu_exact(float v) {
    return 0.5f * v * (1.0f + erff(v * 0.70710678118654752f));
}
__device__ __forceinline__ void split_f16(float v, __half& h, __half& l) {
    h = __float2half_rn(v);
    l = __float2half_rn(v - __half2float(h));
}
__device__ __forceinline__ uint32_t pack_f16(__half a, __half b) {
    return ((uint32_t)__half_as_ushort(b) << 16) | (uint32_t)__half_as_ushort(a);
}
__device__ __forceinline__ uint32_t smem_u32(const void* p) {
    uint32_t a;
    asm("{ .reg .u64 t; cvta.to.shared.u64 t, %1; cvt.u32.u64 %0, t; }" : "=r"(a) : "l"(p));
    return a;
}

#define LDM_X4(r0,r1,r2,r3,addr) \
    asm volatile("ldmatrix.sync.aligned.m8n8.x4.shared.b16 {%0,%1,%2,%3}, [%4];" \
        : "=r"(r0),"=r"(r1),"=r"(r2),"=r"(r3) : "r"(addr))
#define LDM_X4T(r0,r1,r2,r3,addr) \
    asm volatile("ldmatrix.sync.aligned.m8n8.x4.trans.shared.b16 {%0,%1,%2,%3}, [%4];" \
        : "=r"(r0),"=r"(r1),"=r"(r2),"=r"(r3) : "r"(addr))

__device__ __forceinline__ void mma_f16(float* c, const uint32_t* a, uint32_t b0, uint32_t b1) {
    asm volatile("mma.sync.aligned.m16n8k16.row.col.f32.f16.f16.f32 "
        "{%0,%1,%2,%3}, {%4,%5,%6,%7}, {%8,%9}, {%0,%1,%2,%3};"
        : "+f"(c[0]), "+f"(c[1]), "+f"(c[2]), "+f"(c[3])
        : "r"(a[0]), "r"(a[1]), "r"(a[2]), "r"(a[3]), "r"(b0), "r"(b1));
}

#define CP_ASYNC16(saddr, gptr) \
    asm volatile("cp.async.cg.shared.global [%0], [%1], 16;" \
        :: "r"(saddr), "l"(__cvta_generic_to_global(gptr)) : "memory")
#define CP_COMMIT() asm volatile("cp.async.commit_group;" ::: "memory")
#define CP_WAIT0()  asm volatile("cp.async.wait_group 0;" ::: "memory")

// Single global barrier: atomicInc wrapping at NBLK-1 -> last arrival sets 0.
__device__ __forceinline__ void gbar() {
    __syncthreads();
    if (threadIdx.x == 0) {
        __threadfence();
        atomicInc(&g_bcnt, NBLK - 1u);
        volatile unsigned* p = &g_bcnt;
        while (*p != 0u) {}
        __threadfence();
    }
    __syncthreads();
}

#define LDA 72
#define TILE (64*LDA)           // 4608 halves
#define FUS_SMEM (10*TILE*2)    // 92160 B -> 2 CTAs/SM

__global__ void __launch_bounds__(256, 2)
k_all(const float* __restrict__ x,   const float* __restrict__ adj,
      const float* __restrict__ ew1, const float* __restrict__ eb1,
      const float* __restrict__ ew2, const float* __restrict__ eb2,
      const float* __restrict__ nw,  const float* __restrict__ nb,
      const float* __restrict__ gw,  const float* __restrict__ gb,
      const float* __restrict__ gms, float* __restrict__ out) {
    extern __shared__ __align__(16) __half ds[];
    int tid = threadIdx.x, blk = blockIdx.x;

    // =================== PHASE A: prologue (rebalanced) ===================
    if (blk < BT) {
        // ---- norm + T2 for bt = blk (exempt from edge/ew2 work) ----
        int bt = blk;
        int f = tid & 63;
        int g = tid >> 6;
        float* sA   = (float*)ds;               // [4][64]
        float* sB   = sA + 256;
        float* sMul = sB + 256;
        float* sSub = sMul + 64;
        float* sAdd = sSub + 64;
        float* sSf  = sAdd + 64;

        const float* xp = x + bt * (Nn * FINn) + f;
        float s = 0.f, ss = 0.f;
#pragma unroll
        for (int n = g * 16; n < g * 16 + 16; n++) {
            float v = xp[n * FINn];
            s += v; ss += v * v;
        }
        sA[g * 64 + f] = s; sB[g * 64 + f] = ss;
        __syncthreads();

        if (g == 0) {
            float st  = sA[f] + sA[64 + f] + sA[128 + f] + sA[192 + f];
            float sst = sB[f] + sB[64 + f] + sB[128 + f] + sB[192 + f];
            float mean = st * (1.0f / Nn);
            float var  = sst * (1.0f / Nn) - mean * mean;
            float rstd = rsqrtf(var + 1e-5f);
            float w = gw[f], bbv = gb[f];
            float sub = mean * gms[0];
            sMul[f] = rstd * w;
            sSub[f] = sub;
            sAdd[f] = bbv;
            sSf[f]  = (float)Nn * ((mean - sub) * rstd * w + bbv);
        }
        __syncthreads();

        float mul = sMul[f], sub = sSub[f], add = sAdd[f];
#pragma unroll
        for (int n = g * 16; n < g * 16 + 16; n++) {
            float v = (xp[n * FINn] - sub) * mul + add;
            __half h, l; split_f16(v, h, l);
            g_xnh[bt * 4096 + n * 64 + f] = h;
            g_xnl[bt * 4096 + n * 64 + f] = l;
        }

        int o = f;
        float acc = 0.f;
#pragma unroll
        for (int ff = g * 16; ff < g * 16 + 16; ff++)
            acc += sSf[ff] * eb2[ff * FOUTn + o];
        __syncthreads();
        sA[g * 64 + o] = acc;
        __syncthreads();
        if (g == 0)
            g_T2[bt * FOUTn + o] = sA[o] + sA[64 + o] + sA[128 + o] + sA[192 + o];
        __syncthreads();
    } else {
        int bi = blk - BT;                      // 0..191
        if (bi < 32) {
            // nw convert: 4096 elems over blocks 64..95
            int idx = bi * 128 + (tid & 127);
            if (tid < 128) g_nw[idx] = __float2half_rn(nw[idx]);
        }
        // edge: 65536 uint32-pairs over 192 blocks (grid-stride)
        for (int p = bi * 256 + tid; p < 65536; p += 192 * 256) {
            int idx2 = p * 2;
            int row = idx2 >> 6;                // (b,e,i)
            int j = idx2 & 63;
            int b = row >> 10, e = (row >> 6) & 15, i = row & 63;
            float2 a2 = *(const float2*)(adj + b * 4096 + i * 64 + j);
            float w1 = ew1[e], b1 = eb1[e];
            __half h0 = __float2half_rn(gelu_exact(a2.x * w1 + b1));
            __half h1 = __float2half_rn(gelu_exact(a2.y * w1 + b1));
            *(uint32_t*)(g_h + idx2) = pack_f16(h0, h1);
        }
        // ew2 convert: 65536 elems over 192 blocks (grid-stride)
        for (int i = bi * 256 + tid; i < 65536; i += 192 * 256)
            g_w2[i] = __float2half_rn(ew2[i]);
    }

    gbar();

    // =================== PHASE B: fused GEMM (paired e) + parallel finisher ===================
    {
        __half *Xh = ds, *Xl = ds + TILE;       // recycled as P0/P1 after frags
        __half *P0 = Xh, *P1 = Xl;
        __half *Wt[2][2] = {{ds + 2*TILE, ds + 3*TILE}, {ds + 4*TILE, ds + 5*TILE}};
        __half *Ht[2][2] = {{ds + 6*TILE, ds + 7*TILE}, {ds + 8*TILE, ds + 9*TILE}};

        int warp = tid >> 5, lane = tid & 31;
        int wr = warp >> 1, wc = warp & 1;
        int bt = blk >> 2, eg = blk & 3;
        int b = bt >> 5;

        // prefetch X tiles + pair 0 (W/H for e0, e1)
        {
            const __half* xhp = g_xnh + bt * 4096;
            const __half* xlp = g_xnl + bt * 4096;
            uint32_t sXh = smem_u32(Xh), sXl = smem_u32(Xl);
#pragma unroll
            for (int l = 0; l < 2; l++) {
                int idx = tid + l * 256;
                int r = idx >> 3, q = idx & 7;
                uint32_t off = (uint32_t)(r * LDA + q * 8) * 2;
                CP_ASYNC16(sXh + off, xhp + r * 64 + q * 8);
                CP_ASYNC16(sXl + off, xlp + r * 64 + q * 8);
            }
#pragma unroll
            for (int e2 = 0; e2 < 2; e2++) {
                int e = eg * 4 + e2;
                uint32_t sW = smem_u32(Wt[0][e2]), sH = smem_u32(Ht[0][e2]);
                const __half* wp = g_w2 + e * 4096;
                const __half* hp = g_h + (b * 16 + e) * 4096;
#pragma unroll
                for (int l = 0; l < 2; l++) {
                    int idx = tid + l * 256;
                    int r = idx >> 3, q = idx & 7;
                    uint32_t off = (uint32_t)(r * LDA + q * 8) * 2;
                    CP_ASYNC16(sW + off, wp + r * 64 + q * 8);
                    CP_ASYNC16(sH + off, hp + r * 64 + q * 8);
                }
            }
            CP_COMMIT();
        }
        CP_WAIT0();
        __syncthreads();

        uint32_t xBh = smem_u32(Xh), xBl = smem_u32(Xl);
        int g = lane >> 3, lr = lane & 7;
        int arow = wr * 16 + (g & 1) * 8 + lr;
        int acol0 = (g >> 1) * 8;

        // persistent xn A-fragments, then X tiles become P0/P1
        uint32_t xh[16], xl[16];
#pragma unroll
        for (int ks = 0; ks < 4; ks++) {
            uint32_t off = (uint32_t)(arow * LDA + ks * 16 + acol0) * 2;
            LDM_X4(xh[4*ks], xh[4*ks+1], xh[4*ks+2], xh[4*ks+3], xBh + off);
            LDM_X4(xl[4*ks], xl[4*ks+1], xl[4*ks+2], xl[4*ks+3], xBl + off);
        }
        __syncthreads();            // all warps done reading X tiles

        // prefetch pair 1 (e2, e3)
        {
#pragma unroll
            for (int e2 = 0; e2 < 2; e2++) {
                int e = eg * 4 + 2 + e2;
                uint32_t sW = smem_u32(Wt[1][e2]), sH = smem_u32(Ht[1][e2]);
                const __half* wp = g_w2 + e * 4096;
                const __half* hp = g_h + (b * 16 + e) * 4096;
#pragma unroll
                for (int l = 0; l < 2; l++) {
                    int idx = tid + l * 256;
                    int r = idx >> 3, q = idx & 7;
                    uint32_t off = (uint32_t)(r * LDA + q * 8) * 2;
                    CP_ASYNC16(sW + off, wp + r * 64 + q * 8);
                    CP_ASYNC16(sH + off, hp + r * 64 + q * 8);
                }
            }
            CP_COMMIT();
        }

        float agg[4][4];
#pragma unroll
        for (int i = 0; i < 4; i++) { agg[i][0]=0.f; agg[i][1]=0.f; agg[i][2]=0.f; agg[i][3]=0.f; }

        int cr = lane >> 2, cc2 = (lane & 3) * 2;
        uint32_t pB[2] = { smem_u32(P0), smem_u32(P1) };

        for (int pp = 0; pp < 2; pp++) {
            // ---- mma1 for both e of the pair: P(e2) = (Xh+Xl) @ W ----
#pragma unroll
            for (int e2 = 0; e2 < 2; e2++) {
                uint32_t wB = smem_u32(Wt[pp][e2]);
                __half* Pt = e2 ? P1 : P0;
#pragma unroll
                for (int nt = 0; nt < 4; nt++) {
                    float p[4] = {0.f,0.f,0.f,0.f};
                    uint32_t bw[8];
                    uint32_t off1 = (uint32_t)((g * 8 + lr) * LDA + wc * 32 + nt * 8) * 2;
                    uint32_t off2 = (uint32_t)((32 + g * 8 + lr) * LDA + wc * 32 + nt * 8) * 2;
                    LDM_X4T(bw[0], bw[1], bw[2], bw[3], wB + off1);
                    LDM_X4T(bw[4], bw[5], bw[6], bw[7], wB + off2);
#pragma unroll
                    for (int ks = 0; ks < 4; ks++) {
                        mma_f16(p, xh + 4*ks, bw[2*ks], bw[2*ks+1]);
                        mma_f16(p, xl + 4*ks, bw[2*ks], bw[2*ks+1]);
                    }
#pragma unroll
                    for (int half = 0; half < 2; half++) {
                        int row = wr * 16 + cr + half * 8;
                        int col = wc * 32 + nt * 8 + cc2;
                        *(uint32_t*)(Pt + row * LDA + col) =
                            pack_f16(__float2half_rn(p[half*2]), __float2half_rn(p[half*2+1]));
                    }
                }
            }
            if (pp == 0) CP_WAIT0();
            __syncthreads();

            // ---- mma2 for both e: agg += h(e) @ P(e) ----
#pragma unroll
            for (int e2 = 0; e2 < 2; e2++) {
                uint32_t hB = smem_u32(Ht[pp][e2]);
                uint32_t ahh[16];
#pragma unroll
                for (int ks = 0; ks < 4; ks++) {
                    uint32_t off = (uint32_t)(arow * LDA + ks * 16 + acol0) * 2;
                    LDM_X4(ahh[4*ks], ahh[4*ks+1], ahh[4*ks+2], ahh[4*ks+3], hB + off);
                }
#pragma unroll
                for (int kh = 0; kh < 2; kh++) {
#pragma unroll
                    for (int nt = 0; nt < 4; nt++) {
                        uint32_t bp[4];
                        uint32_t off = (uint32_t)((kh * 32 + g * 8 + lr) * LDA + wc * 32 + nt * 8) * 2;
                        LDM_X4T(bp[0], bp[1], bp[2], bp[3], pB[e2] + off);
#pragma unroll
                        for (int k2 = 0; k2 < 2; k2++) {
                            int ks = kh * 2 + k2;
                            mma_f16(agg[nt], ahh + 4*ks, bp[2*k2], bp[2*k2+1]);
                        }
                    }
                }
            }
            __syncthreads();
        }

        // ---- node-lin quarter: agg += (Xh+Xl) @ nw[:, eg*16..+16) ----
        if (tid < 128) {
            int r = tid >> 1, hf = tid & 1;
            *(uint4*)(Wt[0][0] + r * LDA + hf * 8) = *(const uint4*)(g_nw + r * 64 + eg * 16 + hf * 8);
        }
        __syncthreads();
        if (wc == (eg >> 1)) {
            uint32_t wB = smem_u32(Wt[0][0]);
            int ntb = (eg & 1) * 2;
#pragma unroll
            for (int kh = 0; kh < 2; kh++) {
#pragma unroll
                for (int ntl = 0; ntl < 2; ntl++) {
                    uint32_t bw[4];
                    uint32_t off = (uint32_t)((kh * 32 + g * 8 + lr) * LDA + ntl * 8) * 2;
                    LDM_X4T(bw[0], bw[1], bw[2], bw[3], wB + off);
#pragma unroll
                    for (int k2 = 0; k2 < 2; k2++) {
                        int ks = kh * 2 + k2;
                        mma_f16(agg[ntb + ntl], xh + 4*ks, bw[2*k2], bw[2*k2+1]);
                        mma_f16(agg[ntb + ntl], xl + 4*ks, bw[2*k2], bw[2*k2+1]);
                    }
                }
            }
        }

        // ---- store partial ----
        float* Cdst = g_part[eg] + bt * (Nn * FOUTn);
#pragma unroll
        for (int nt = 0; nt < 4; nt++) {
            int col = wc * 32 + nt * 8 + cc2;
            *(float2*)(Cdst + (wr * 16 + cr) * FOUTn + col)     = make_float2(agg[nt][0], agg[nt][1]);
            *(float2*)(Cdst + (wr * 16 + cr + 8) * FOUTn + col) = make_float2(agg[nt][2], agg[nt][3]);
        }

        // ---- per-bt barrier (wrap at 3 -> ends 0), then all 4 blocks write quarters ----
        __threadfence();
        __syncthreads();
        if (tid == 0) {
            atomicInc(&g_btcnt[bt], 3u);
            volatile unsigned* p = &g_btcnt[bt];
            while (*p != 0u) {}
            __threadfence();
        }
        __syncthreads();
        {
            int idx = eg * 256 + tid;             // quarter: 256 float4 per block
            int e0 = bt * 4096 + idx * 4;
            int o  = (idx * 4) & 63;
            float4 p0 = *(const float4*)(g_part[0] + e0);
            float4 p1 = *(const float4*)(g_part[1] + e0);
            float4 p2 = *(const float4*)(g_part[2] + e0);
            float4 p3 = *(const float4*)(g_part[3] + e0);
            float4 nbv = *(const float4*)(nb + o);
            float4 t2v = *(const float4*)(g_T2 + bt * FOUTn + o);
            float v0 = p0.x + p1.x + p2.x + p3.x + nbv.x + t2v.x;
            float v1 = p0.y + p1.y + p2.y + p3.y + nbv.y + t2v.y;
            float v2 = p0.z + p1.z + p2.z + p3.z + nbv.z + t2v.z;
            float v3 = p0.w + p1.w + p2.w + p3.w + nbv.w + t2v.w;
            *(float4*)(out + e0) = make_float4(gelu_exact(v0), gelu_exact(v1),
                                               gelu_exact(v2), gelu_exact(v3));
        }
    }
}

extern "C" void kernel_launch(void* const* d_in, const int* in_sizes, int n_in,
                              void* d_out, int out_size) {
    const float* x   = (const float*)d_in[0];
    const float* adj = (const float*)d_in[1];
    const float* ew1 = (const float*)d_in[2];
    const float* eb1 = (const float*)d_in[3];
    const float* ew2 = (const float*)d_in[4];
    const float* eb2 = (const float*)d_in[5];
    const float* nw  = (const float*)d_in[6];
    const float* nb  = (const float*)d_in[7];
    const float* gw  = (const float*)d_in[8];
    const float* gb  = (const float*)d_in[9];
    const float* gms = (const float*)d_in[10];
    float* out = (float*)d_out;

    cudaFuncSetAttribute(k_all, cudaFuncAttributeMaxDynamicSharedMemorySize, FUS_SMEM);
    k_all<<<NBLK, 256, FUS_SMEM>>>(x, adj, ew1, eb1, ew2, eb2, nw, nb, gw, gb, gms, out);
}

// round 15
// speedup vs baseline: 1.3205x; 1.0017x over previous
#include <cuda_runtime.h>
#include <cuda_fp16.h>
#include <math.h>
#include <stdint.h>

// Problem constants
#define Bn 2
#define Tn 32
#define Nn 64
#define FINn 64
#define FOUTn 64
#define EDIMn 16
#define BT (Bn*Tn)            // 64
#define ROWS (BT*Nn)          // 4096
#define NBLK 256              // all CTAs co-resident: 2/SM * 296 >= 256

// -------- device scratch --------
__device__ __half g_xnh[ROWS*FINn];        // xn fp16 [bt*64+j][f]
__device__ __half g_h[Bn*EDIMn*Nn*Nn];     // h fp16 [b][e][i][j]
__device__ __half g_w2[EDIMn*FINn*FOUTn];  // ew2 fp16 [e][f][o]
__device__ __half g_nw[FINn*FOUTn];        // nw fp16 [f][o]
__device__ float g_part[4][BT*Nn*FOUTn];   // per-eg partials (node-lin in eg0)
__device__ float g_T2[BT*FOUTn];           // eb2 contribution
__device__ unsigned g_bcnt;                // global barrier counter (ends at 0)
__device__ unsigned g_btcnt[BT];           // per-bt completion counters (end at 0)

__device__ __forceinline__ float gelu_exact(float v) {
    return 0.5f * v * (1.0f + erff(v * 0.70710678118654752f));
}
__device__ __forceinline__ uint32_t pack_f16(__half a, __half b) {
    return ((uint32_t)__half_as_ushort(b) << 16) | (uint32_t)__half_as_ushort(a);
}
__device__ __forceinline__ uint32_t smem_u32(const void* p) {
    uint32_t a;
    asm("{ .reg .u64 t; cvta.to.shared.u64 t, %1; cvt.u32.u64 %0, t; }" : "=r"(a) : "l"(p));
    return a;
}

#define LDM_X4(r0,r1,r2,r3,addr) \
    asm volatile("ldmatrix.sync.aligned.m8n8.x4.shared.b16 {%0,%1,%2,%3}, [%4];" \
        : "=r"(r0),"=r"(r1),"=r"(r2),"=r"(r3) : "r"(addr))
#define LDM_X4T(r0,r1,r2,r3,addr) \
    asm volatile("ldmatrix.sync.aligned.m8n8.x4.trans.shared.b16 {%0,%1,%2,%3}, [%4];" \
        : "=r"(r0),"=r"(r1),"=r"(r2),"=r"(r3) : "r"(addr))

__device__ __forceinline__ void mma_f16(float* c, const uint32_t* a, uint32_t b0, uint32_t b1) {
    asm volatile("mma.sync.aligned.m16n8k16.row.col.f32.f16.f16.f32 "
        "{%0,%1,%2,%3}, {%4,%5,%6,%7}, {%8,%9}, {%0,%1,%2,%3};"
        : "+f"(c[0]), "+f"(c[1]), "+f"(c[2]), "+f"(c[3])
        : "r"(a[0]), "r"(a[1]), "r"(a[2]), "r"(a[3]), "r"(b0), "r"(b1));
}

#define CP_ASYNC16(saddr, gptr) \
    asm volatile("cp.async.cg.shared.global [%0], [%1], 16;" \
        :: "r"(saddr), "l"(__cvta_generic_to_global(gptr)) : "memory")
#define CP_COMMIT() asm volatile("cp.async.commit_group;" ::: "memory")
#define CP_WAIT0()  asm volatile("cp.async.wait_group 0;" ::: "memory")

// Single global barrier: atomicInc wrapping at NBLK-1 -> last arrival sets 0.
__device__ __forceinline__ void gbar() {
    __syncthreads();
    if (threadIdx.x == 0) {
        __threadfence();
        atomicInc(&g_bcnt, NBLK - 1u);
        volatile unsigned* p = &g_bcnt;
        while (*p != 0u) {}
        __threadfence();
    }
    __syncthreads();
}

#define LDA 72
#define TILE (64*LDA)           // 4608 halves
#define FUS_SMEM (10*TILE*2)    // 92160 B -> 2 CTAs/SM

__global__ void __launch_bounds__(256, 2)
k_all(const float* __restrict__ x,   const float* __restrict__ adj,
      const float* __restrict__ ew1, const float* __restrict__ eb1,
      const float* __restrict__ ew2, const float* __restrict__ eb2,
      const float* __restrict__ nw,  const float* __restrict__ nb,
      const float* __restrict__ gw,  const float* __restrict__ gb,
      const float* __restrict__ gms, float* __restrict__ out) {
    extern __shared__ __align__(16) __half ds[];
    __shared__ unsigned s_old;
    int tid = threadIdx.x, blk = blockIdx.x;

    // =================== PHASE A: prologue ===================
    if (blk < BT) {
        // ---- norm + T2 for bt = blk ----
        int bt = blk;
        int f = tid & 63;
        int g = tid >> 6;
        float* sA   = (float*)ds;               // [4][64]
        float* sB   = sA + 256;
        float* sMul = sB + 256;
        float* sSub = sMul + 64;
        float* sAdd = sSub + 64;
        float* sSf  = sAdd + 64;

        const float* xp = x + bt * (Nn * FINn) + f;
        float s = 0.f, ss = 0.f;
#pragma unroll
        for (int n = g * 16; n < g * 16 + 16; n++) {
            float v = xp[n * FINn];
            s += v; ss += v * v;
        }
        sA[g * 64 + f] = s; sB[g * 64 + f] = ss;
        __syncthreads();

        if (g == 0) {
            float st  = sA[f] + sA[64 + f] + sA[128 + f] + sA[192 + f];
            float sst = sB[f] + sB[64 + f] + sB[128 + f] + sB[192 + f];
            float mean = st * (1.0f / Nn);
            float var  = sst * (1.0f / Nn) - mean * mean;
            float rstd = rsqrtf(var + 1e-5f);
            float w = gw[f], bbv = gb[f];
            float sub = mean * gms[0];
            sMul[f] = rstd * w;
            sSub[f] = sub;
            sAdd[f] = bbv;
            sSf[f]  = (float)Nn * ((mean - sub) * rstd * w + bbv);
        }
        __syncthreads();

        float mul = sMul[f], sub = sSub[f], add = sAdd[f];
#pragma unroll
        for (int n = g * 16; n < g * 16 + 16; n++) {
            float v = (xp[n * FINn] - sub) * mul + add;
            g_xnh[bt * 4096 + n * 64 + f] = __float2half_rn(v);
        }

        int o = f;
        float acc = 0.f;
#pragma unroll
        for (int ff = g * 16; ff < g * 16 + 16; ff++)
            acc += sSf[ff] * eb2[ff * FOUTn + o];
        __syncthreads();
        sA[g * 64 + o] = acc;
        __syncthreads();
        if (g == 0)
            g_T2[bt * FOUTn + o] = sA[o] + sA[64 + o] + sA[128 + o] + sA[192 + o];
        __syncthreads();
    } else if (blk < BT + 16) {
        // nw convert: 4096 elems over blocks 64..79
        int idx = (blk - BT) * 256 + tid;
        g_nw[idx] = __float2half_rn(nw[idx]);
    }

    // edge (all blocks): 131072 elems, 2/thread, fp16
    {
        int idx2 = blk * 512 + tid * 2;
        int row = idx2 >> 6;                    // (b,e,i)
        int j = idx2 & 63;
        int b = row >> 10, e = (row >> 6) & 15, i = row & 63;
        float2 a2 = *(const float2*)(adj + b * 4096 + i * 64 + j);
        float w1 = ew1[e], b1 = eb1[e];
        __half h0 = __float2half_rn(gelu_exact(a2.x * w1 + b1));
        __half h1 = __float2half_rn(gelu_exact(a2.y * w1 + b1));
        *(uint32_t*)(g_h + idx2) = pack_f16(h0, h1);
    }
    // ew2 convert (all blocks): 65536 elems, 1/thread
    {
        int idx = blk * 256 + tid;
        g_w2[idx] = __float2half_rn(ew2[idx]);
    }

    gbar();

    // =================== PHASE B: fused GEMM (paired e) + finisher ===================
    {
        __half *Xh = ds;                         // recycled as P0 after frags
        __half *P0 = Xh, *P1 = ds + TILE;
        __half *Wt[2][2] = {{ds + 2*TILE, ds + 3*TILE}, {ds + 4*TILE, ds + 5*TILE}};
        __half *Ht[2][2] = {{ds + 6*TILE, ds + 7*TILE}, {ds + 8*TILE, ds + 9*TILE}};

        int warp = tid >> 5, lane = tid & 31;
        int wr = warp >> 1, wc = warp & 1;
        int bt = blk >> 2, eg = blk & 3;
        int b = bt >> 5;

        // prefetch X tile + pair 0 (W/H for e0, e1)
        {
            const __half* xhp = g_xnh + bt * 4096;
            uint32_t sXh = smem_u32(Xh);
#pragma unroll
            for (int l = 0; l < 2; l++) {
                int idx = tid + l * 256;
                int r = idx >> 3, q = idx & 7;
                uint32_t off = (uint32_t)(r * LDA + q * 8) * 2;
                CP_ASYNC16(sXh + off, xhp + r * 64 + q * 8);
            }
#pragma unroll
            for (int e2 = 0; e2 < 2; e2++) {
                int e = eg * 4 + e2;
                uint32_t sW = smem_u32(Wt[0][e2]), sH = smem_u32(Ht[0][e2]);
                const __half* wp = g_w2 + e * 4096;
                const __half* hp = g_h + (b * 16 + e) * 4096;
#pragma unroll
                for (int l = 0; l < 2; l++) {
                    int idx = tid + l * 256;
                    int r = idx >> 3, q = idx & 7;
                    uint32_t off = (uint32_t)(r * LDA + q * 8) * 2;
                    CP_ASYNC16(sW + off, wp + r * 64 + q * 8);
                    CP_ASYNC16(sH + off, hp + r * 64 + q * 8);
                }
            }
            CP_COMMIT();
        }
        CP_WAIT0();
        __syncthreads();

        uint32_t xBh = smem_u32(Xh);
        int g = lane >> 3, lr = lane & 7;
        int arow = wr * 16 + (g & 1) * 8 + lr;
        int acol0 = (g >> 1) * 8;

        // persistent xn A-fragments, then X tile becomes P0
        uint32_t xh[16];
#pragma unroll
        for (int ks = 0; ks < 4; ks++) {
            uint32_t off = (uint32_t)(arow * LDA + ks * 16 + acol0) * 2;
            LDM_X4(xh[4*ks], xh[4*ks+1], xh[4*ks+2], xh[4*ks+3], xBh + off);
        }
        __syncthreads();            // all warps done reading X tile

        // prefetch pair 1 (e2, e3)
        {
#pragma unroll
            for (int e2 = 0; e2 < 2; e2++) {
                int e = eg * 4 + 2 + e2;
                uint32_t sW = smem_u32(Wt[1][e2]), sH = smem_u32(Ht[1][e2]);
                const __half* wp = g_w2 + e * 4096;
                const __half* hp = g_h + (b * 16 + e) * 4096;
#pragma unroll
                for (int l = 0; l < 2; l++) {
                    int idx = tid + l * 256;
                    int r = idx >> 3, q = idx & 7;
                    uint32_t off = (uint32_t)(r * LDA + q * 8) * 2;
                    CP_ASYNC16(sW + off, wp + r * 64 + q * 8);
                    CP_ASYNC16(sH + off, hp + r * 64 + q * 8);
                }
            }
            CP_COMMIT();
        }

        float agg[4][4];
#pragma unroll
        for (int i = 0; i < 4; i++) { agg[i][0]=0.f; agg[i][1]=0.f; agg[i][2]=0.f; agg[i][3]=0.f; }

        int cr = lane >> 2, cc2 = (lane & 3) * 2;
        uint32_t pB[2] = { smem_u32(P0), smem_u32(P1) };

        for (int pp = 0; pp < 2; pp++) {
            // ---- mma1 for both e of the pair: P(e2) = Xh @ W ----
#pragma unroll
            for (int e2 = 0; e2 < 2; e2++) {
                uint32_t wB = smem_u32(Wt[pp][e2]);
                __half* Pt = e2 ? P1 : P0;
#pragma unroll
                for (int nt = 0; nt < 4; nt++) {
                    float p[4] = {0.f,0.f,0.f,0.f};
                    uint32_t bw[8];
                    uint32_t off1 = (uint32_t)((g * 8 + lr) * LDA + wc * 32 + nt * 8) * 2;
                    uint32_t off2 = (uint32_t)((32 + g * 8 + lr) * LDA + wc * 32 + nt * 8) * 2;
                    LDM_X4T(bw[0], bw[1], bw[2], bw[3], wB + off1);
                    LDM_X4T(bw[4], bw[5], bw[6], bw[7], wB + off2);
#pragma unroll
                    for (int ks = 0; ks < 4; ks++)
                        mma_f16(p, xh + 4*ks, bw[2*ks], bw[2*ks+1]);
#pragma unroll
                    for (int half = 0; half < 2; half++) {
                        int row = wr * 16 + cr + half * 8;
                        int col = wc * 32 + nt * 8 + cc2;
                        *(uint32_t*)(Pt + row * LDA + col) =
                            pack_f16(__float2half_rn(p[half*2]), __float2half_rn(p[half*2+1]));
                    }
                }
            }
            if (pp == 0) CP_WAIT0();
            __syncthreads();

            // ---- mma2 for both e: agg += h(e) @ P(e) ----
#pragma unroll
            for (int e2 = 0; e2 < 2; e2++) {
                uint32_t hB = smem_u32(Ht[pp][e2]);
                uint32_t ahh[16];
#pragma unroll
                for (int ks = 0; ks < 4; ks++) {
                    uint32_t off = (uint32_t)(arow * LDA + ks * 16 + acol0) * 2;
                    LDM_X4(ahh[4*ks], ahh[4*ks+1], ahh[4*ks+2], ahh[4*ks+3], hB + off);
                }
#pragma unroll
                for (int kh = 0; kh < 2; kh++) {
#pragma unroll
                    for (int nt = 0; nt < 4; nt++) {
                        uint32_t bp[4];
                        uint32_t off = (uint32_t)((kh * 32 + g * 8 + lr) * LDA + wc * 32 + nt * 8) * 2;
                        LDM_X4T(bp[0], bp[1], bp[2], bp[3], pB[e2] + off);
#pragma unroll
                        for (int k2 = 0; k2 < 2; k2++) {
                            int ks = kh * 2 + k2;
                            mma_f16(agg[nt], ahh + 4*ks, bp[2*k2], bp[2*k2+1]);
                        }
                    }
                }
            }
            __syncthreads();
        }

        // ---- eg 0: node-lin  agg += Xh @ nw ----
        if (eg == 0) {
#pragma unroll
            for (int l = 0; l < 2; l++) {
                int idx = tid + l * 256;
                int r = idx >> 3, q = idx & 7;
                *(uint4*)(Wt[0][0] + r * LDA + q * 8) = *(const uint4*)(g_nw + r * 64 + q * 8);
            }
            __syncthreads();
            uint32_t wB = smem_u32(Wt[0][0]);
#pragma unroll
            for (int kh = 0; kh < 2; kh++) {
#pragma unroll
                for (int nt = 0; nt < 4; nt++) {
                    uint32_t bw[4];
                    uint32_t off = (uint32_t)((kh * 32 + g * 8 + lr) * LDA + wc * 32 + nt * 8) * 2;
                    LDM_X4T(bw[0], bw[1], bw[2], bw[3], wB + off);
#pragma unroll
                    for (int k2 = 0; k2 < 2; k2++) {
                        int ks = kh * 2 + k2;
                        mma_f16(agg[nt], xh + 4*ks, bw[2*k2], bw[2*k2+1]);
                    }
                }
            }
        }

        // ---- store partial ----
        float* Cdst = g_part[eg] + bt * (Nn * FOUTn);
#pragma unroll
        for (int nt = 0; nt < 4; nt++) {
            int col = wc * 32 + nt * 8 + cc2;
            *(float2*)(Cdst + (wr * 16 + cr) * FOUTn + col)     = make_float2(agg[nt][0], agg[nt][1]);
            *(float2*)(Cdst + (wr * 16 + cr + 8) * FOUTn + col) = make_float2(agg[nt][2], agg[nt][3]);
        }

        // ---- per-bt finisher: last of 4 eg-blocks sums + gelu + out ----
        __threadfence();
        __syncthreads();
        if (tid == 0) s_old = atomicAdd(&g_btcnt[bt], 1u);
        __syncthreads();
        if (s_old == 3u) {
            __threadfence();
            int base = bt * (Nn * FOUTn);
#pragma unroll
            for (int l = 0; l < 4; l++) {
                int idx = tid + l * 256;          // 1024 float4 tasks for this bt
                int e0 = base + idx * 4;
                int o  = (idx * 4) & 63;
                float4 p0 = *(const float4*)(g_part[0] + e0);
                float4 p1 = *(const float4*)(g_part[1] + e0);
                float4 p2 = *(const float4*)(g_part[2] + e0);
                float4 p3 = *(const float4*)(g_part[3] + e0);
                float4 nbv = *(const float4*)(nb + o);
                float4 t2v = *(const float4*)(g_T2 + bt * FOUTn + o);
                float v0 = p0.x + p1.x + p2.x + p3.x + nbv.x + t2v.x;
                float v1 = p0.y + p1.y + p2.y + p3.y + nbv.y + t2v.y;
                float v2 = p0.z + p1.z + p2.z + p3.z + nbv.z + t2v.z;
                float v3 = p0.w + p1.w + p2.w + p3.w + nbv.w + t2v.w;
                *(float4*)(out + e0) = make_float4(gelu_exact(v0), gelu_exact(v1),
                                                   gelu_exact(v2), gelu_exact(v3));
            }
            if (tid == 0) g_btcnt[bt] = 0;        // reset for next graph replay
        }
    }
}

extern "C" void kernel_launch(void* const* d_in, const int* in_sizes, int n_in,
                              void* d_out, int out_size) {
    const float* x   = (const float*)d_in[0];
    const float* adj = (const float*)d_in[1];
    const float* ew1 = (const float*)d_in[2];
    const float* eb1 = (const float*)d_in[3];
    const float* ew2 = (const float*)d_in[4];
    const float* eb2 = (const float*)d_in[5];
    const float* nw  = (const float*)d_in[6];
    const float* nb  = (const float*)d_in[7];
    const float* gw  = (const float*)d_in[8];
    const float* gb  = (const float*)d_in[9];
    const float* gms = (const float*)d_in[10];
    float* out = (float*)d_out;

    cudaFuncSetAttribute(k_all, cudaFuncAttributeMaxDynamicSharedMemorySize, FUS_SMEM);
    k_all<<<NBLK, 256, FUS_SMEM>>>(x, adj, ew1, eb1, ew2, eb2, nw, nb, gw, gb, gms, out);
}

// round 16
// speedup vs baseline: 1.4981x; 1.1345x over previous
#include <cuda_runtime.h>
#include <cuda_fp16.h>
#include <math.h>
#include <stdint.h>

// Problem constants
#define Bn 2
#define Tn 32
#define Nn 64
#define FINn 64
#define FOUTn 64
#define EDIMn 16
#define BT (Bn*Tn)            // 64
#define ROWS (BT*Nn)          // 4096
#define NBLK 256              // all CTAs co-resident: 2/SM * 148 = 296 >= 256

// -------- device scratch --------
__device__ __half g_xnh[ROWS*FINn];        // xn fp16 [bt*64+j][f]
__device__ __half g_h[Bn*EDIMn*Nn*Nn];     // h fp16 [b][e][i][j]
__device__ __half g_w2[EDIMn*FINn*FOUTn];  // ew2 fp16 [e][f][o]
__device__ __half g_nw[FINn*FOUTn];        // nw fp16 [f][o]
__device__ float g_part[4][BT*Nn*FOUTn];   // per-eg partials (node-lin in eg0)
__device__ float g_T2[BT*FOUTn];           // eb2 contribution
__device__ unsigned g_bcnt;                // global barrier counter (ends at 0)
__device__ unsigned g_btcnt[BT];           // per-bt completion counters (end at 0)

__device__ __forceinline__ float gelu_exact(float v) {
    return 0.5f * v * (1.0f + erff(v * 0.70710678118654752f));
}
__device__ __forceinline__ uint32_t pack_f16(__half a, __half b) {
    return ((uint32_t)__half_as_ushort(b) << 16) | (uint32_t)__half_as_ushort(a);
}
__device__ __forceinline__ uint32_t smem_u32(const void* p) {
    uint32_t a;
    asm("{ .reg .u64 t; cvta.to.shared.u64 t, %1; cvt.u32.u64 %0, t; }" : "=r"(a) : "l"(p));
    return a;
}

#define LDM_X4(r0,r1,r2,r3,addr) \
    asm volatile("ldmatrix.sync.aligned.m8n8.x4.shared.b16 {%0,%1,%2,%3}, [%4];" \
        : "=r"(r0),"=r"(r1),"=r"(r2),"=r"(r3) : "r"(addr))
#define LDM_X4T(r0,r1,r2,r3,addr) \
    asm volatile("ldmatrix.sync.aligned.m8n8.x4.trans.shared.b16 {%0,%1,%2,%3}, [%4];" \
        : "=r"(r0),"=r"(r1),"=r"(r2),"=r"(r3) : "r"(addr))

__device__ __forceinline__ void mma_f16(float* c, const uint32_t* a, uint32_t b0, uint32_t b1) {
    asm volatile("mma.sync.aligned.m16n8k16.row.col.f32.f16.f16.f32 "
        "{%0,%1,%2,%3}, {%4,%5,%6,%7}, {%8,%9}, {%0,%1,%2,%3};"
        : "+f"(c[0]), "+f"(c[1]), "+f"(c[2]), "+f"(c[3])
        : "r"(a[0]), "r"(a[1]), "r"(a[2]), "r"(a[3]), "r"(b0), "r"(b1));
}

#define CP_ASYNC16(saddr, gptr) \
    asm volatile("cp.async.cg.shared.global [%0], [%1], 16;" \
        :: "r"(saddr), "l"(__cvta_generic_to_global(gptr)) : "memory")
#define CP_COMMIT() asm volatile("cp.async.commit_group;" ::: "memory")
#define CP_WAIT0()  asm volatile("cp.async.wait_group 0;" ::: "memory")

// Single global barrier: atomicInc wrapping at NBLK-1 -> last arrival sets 0.
__device__ __forceinline__ void gbar() {
    __syncthreads();
    if (threadIdx.x == 0) {
        __threadfence();
        atomicInc(&g_bcnt, NBLK - 1u);
        volatile unsigned* p = &g_bcnt;
        while (*p != 0u) {}
        __threadfence();
    }
    __syncthreads();
}

#define LDA 72
#define TILE (64*LDA)           // 4608 halves = 9216 B
#define FUS_SMEM (11*TILE*2)    // 101376 B -> still 2 CTAs/SM (2*99 KB < 228 KB)

__global__ void __launch_bounds__(256, 2)
k_all(const float* __restrict__ x,   const float* __restrict__ adj,
      const float* __restrict__ ew1, const float* __restrict__ eb1,
      const float* __restrict__ ew2, const float* __restrict__ eb2,
      const float* __restrict__ nw,  const float* __restrict__ nb,
      const float* __restrict__ gw,  const float* __restrict__ gb,
      const float* __restrict__ gms, float* __restrict__ out) {
    extern __shared__ __align__(16) __half ds[];
    __shared__ unsigned s_old;
    int tid = threadIdx.x, blk = blockIdx.x;

    // =================== PHASE A: prologue ===================
    if (blk < BT) {
        // ---- norm + T2 for bt = blk ----
        int bt = blk;
        int f = tid & 63;
        int g = tid >> 6;
        float* sA   = (float*)ds;               // [4][64]
        float* sB   = sA + 256;
        float* sMul = sB + 256;
        float* sSub = sMul + 64;
        float* sAdd = sSub + 64;
        float* sSf  = sAdd + 64;

        const float* xp = x + bt * (Nn * FINn) + f;
        float s = 0.f, ss = 0.f;
#pragma unroll
        for (int n = g * 16; n < g * 16 + 16; n++) {
            float v = xp[n * FINn];
            s += v; ss += v * v;
        }
        sA[g * 64 + f] = s; sB[g * 64 + f] = ss;
        __syncthreads();

        if (g == 0) {
            float st  = sA[f] + sA[64 + f] + sA[128 + f] + sA[192 + f];
            float sst = sB[f] + sB[64 + f] + sB[128 + f] + sB[192 + f];
            float mean = st * (1.0f / Nn);
            float var  = sst * (1.0f / Nn) - mean * mean;
            float rstd = rsqrtf(var + 1e-5f);
            float w = gw[f], bbv = gb[f];
            float sub = mean * gms[0];
            sMul[f] = rstd * w;
            sSub[f] = sub;
            sAdd[f] = bbv;
            sSf[f]  = (float)Nn * ((mean - sub) * rstd * w + bbv);
        }
        __syncthreads();

        float mul = sMul[f], sub = sSub[f], add = sAdd[f];
#pragma unroll
        for (int n = g * 16; n < g * 16 + 16; n++) {
            float v = (xp[n * FINn] - sub) * mul + add;
            g_xnh[bt * 4096 + n * 64 + f] = __float2half_rn(v);
        }

        int o = f;
        float acc = 0.f;
#pragma unroll
        for (int ff = g * 16; ff < g * 16 + 16; ff++)
            acc += sSf[ff] * eb2[ff * FOUTn + o];
        __syncthreads();
        sA[g * 64 + o] = acc;
        __syncthreads();
        if (g == 0)
            g_T2[bt * FOUTn + o] = sA[o] + sA[64 + o] + sA[128 + o] + sA[192 + o];
        __syncthreads();
    } else if (blk < BT + 16) {
        // nw convert: 4096 elems over blocks 64..79
        int idx = (blk - BT) * 256 + tid;
        g_nw[idx] = __float2half_rn(nw[idx]);
    }

    // edge (all blocks): 131072 elems, 2/thread, fp16
    {
        int idx2 = blk * 512 + tid * 2;
        int row = idx2 >> 6;                    // (b,e,i)
        int j = idx2 & 63;
        int b = row >> 10, e = (row >> 6) & 15, i = row & 63;
        float2 a2 = *(const float2*)(adj + b * 4096 + i * 64 + j);
        float w1 = ew1[e], b1 = eb1[e];
        __half h0 = __float2half_rn(gelu_exact(a2.x * w1 + b1));
        __half h1 = __float2half_rn(gelu_exact(a2.y * w1 + b1));
        *(uint32_t*)(g_h + idx2) = pack_f16(h0, h1);
    }
    // ew2 convert (all blocks): 65536 elems, 1/thread
    {
        int idx = blk * 256 + tid;
        g_w2[idx] = __float2half_rn(ew2[idx]);
    }

    gbar();

    // =================== PHASE B: single-burst fused GEMM + finisher ===================
    {
        // Tile map: T0 = X (-> P0), T1 = P1, T2..T5 = W0..W3 (T2,T3 -> P2,P3),
        //           T6..T9 = H0..H3, T10 = NW (eg0 only)
        __half *Xs = ds;
        __half *Pt01[2] = { ds, ds + TILE };
        __half *Wt[4] = { ds + 2*TILE, ds + 3*TILE, ds + 4*TILE, ds + 5*TILE };
        __half *Pt23[2] = { ds + 2*TILE, ds + 3*TILE };     // recycle W0, W1
        __half *Ht[4] = { ds + 6*TILE, ds + 7*TILE, ds + 8*TILE, ds + 9*TILE };
        __half *NWt = ds + 10*TILE;

        int warp = tid >> 5, lane = tid & 31;
        int wr = warp >> 1, wc = warp & 1;
        int bt = blk >> 2, eg = blk & 3;
        int b = bt >> 5;

        // ---- single burst: X + W0..3 + H0..3 (+ NW for eg0) ----
        {
            const __half* xhp = g_xnh + bt * 4096;
            uint32_t sX = smem_u32(Xs);
#pragma unroll
            for (int l = 0; l < 2; l++) {
                int idx = tid + l * 256;
                int r = idx >> 3, q = idx & 7;
                uint32_t off = (uint32_t)(r * LDA + q * 8) * 2;
                CP_ASYNC16(sX + off, xhp + r * 64 + q * 8);
            }
#pragma unroll
            for (int e2 = 0; e2 < 4; e2++) {
                int e = eg * 4 + e2;
                uint32_t sW = smem_u32(Wt[e2]), sH = smem_u32(Ht[e2]);
                const __half* wp = g_w2 + e * 4096;
                const __half* hp = g_h + (b * 16 + e) * 4096;
#pragma unroll
                for (int l = 0; l < 2; l++) {
                    int idx = tid + l * 256;
                    int r = idx >> 3, q = idx & 7;
                    uint32_t off = (uint32_t)(r * LDA + q * 8) * 2;
                    CP_ASYNC16(sW + off, wp + r * 64 + q * 8);
                    CP_ASYNC16(sH + off, hp + r * 64 + q * 8);
                }
            }
            if (eg == 0) {
                uint32_t sNW = smem_u32(NWt);
#pragma unroll
                for (int l = 0; l < 2; l++) {
                    int idx = tid + l * 256;
                    int r = idx >> 3, q = idx & 7;
                    CP_ASYNC16(sNW + (uint32_t)(r * LDA + q * 8) * 2, g_nw + r * 64 + q * 8);
                }
            }
            CP_COMMIT();
        }
        CP_WAIT0();
        __syncthreads();                        // sync 1: all tiles resident

        uint32_t xB = smem_u32(Xs);
        int g = lane >> 3, lr = lane & 7;
        int arow = wr * 16 + (g & 1) * 8 + lr;
        int acol0 = (g >> 1) * 8;

        // persistent xn A-fragments; X tile then becomes P0
        uint32_t xh[16];
#pragma unroll
        for (int ks = 0; ks < 4; ks++) {
            uint32_t off = (uint32_t)(arow * LDA + ks * 16 + acol0) * 2;
            LDM_X4(xh[4*ks], xh[4*ks+1], xh[4*ks+2], xh[4*ks+3], xB + off);
        }
        __syncthreads();                        // sync 2: X reads complete

        float agg[4][4];
#pragma unroll
        for (int i = 0; i < 4; i++) { agg[i][0]=0.f; agg[i][1]=0.f; agg[i][2]=0.f; agg[i][3]=0.f; }

        int cr = lane >> 2, cc2 = (lane & 3) * 2;

        // ---- helper lambdas unrolled manually: mma1 into Pdst, mma2 from Hsrc/Psrc ----
#define DO_MMA1(WSRC, PDST)                                                    \
        {                                                                      \
            uint32_t wB = smem_u32(WSRC);                                      \
            __half* Pt = (PDST);                                               \
            _Pragma("unroll")                                                  \
            for (int nt = 0; nt < 4; nt++) {                                   \
                float p[4] = {0.f,0.f,0.f,0.f};                                \
                uint32_t bw[8];                                                \
                uint32_t off1 = (uint32_t)((g * 8 + lr) * LDA + wc * 32 + nt * 8) * 2;        \
                uint32_t off2 = (uint32_t)((32 + g * 8 + lr) * LDA + wc * 32 + nt * 8) * 2;   \
                LDM_X4T(bw[0], bw[1], bw[2], bw[3], wB + off1);                \
                LDM_X4T(bw[4], bw[5], bw[6], bw[7], wB + off2);                \
                _Pragma("unroll")                                              \
                for (int ks = 0; ks < 4; ks++)                                 \
                    mma_f16(p, xh + 4*ks, bw[2*ks], bw[2*ks+1]);               \
                _Pragma("unroll")                                              \
                for (int half = 0; half < 2; half++) {                         \
                    int row = wr * 16 + cr + half * 8;                         \
                    int col = wc * 32 + nt * 8 + cc2;                          \
                    *(uint32_t*)(Pt + row * LDA + col) =                       \
                        pack_f16(__float2half_rn(p[half*2]), __float2half_rn(p[half*2+1])); \
                }                                                              \
            }                                                                  \
        }

#define DO_MMA2(HSRC, PSRC)                                                    \
        {                                                                      \
            uint32_t hB = smem_u32(HSRC);                                      \
            uint32_t pBq = smem_u32(PSRC);                                     \
            uint32_t ahh[16];                                                  \
            _Pragma("unroll")                                                  \
            for (int ks = 0; ks < 4; ks++) {                                   \
                uint32_t off = (uint32_t)(arow * LDA + ks * 16 + acol0) * 2;   \
                LDM_X4(ahh[4*ks], ahh[4*ks+1], ahh[4*ks+2], ahh[4*ks+3], hB + off); \
            }                                                                  \
            _Pragma("unroll")                                                  \
            for (int kh = 0; kh < 2; kh++) {                                   \
                _Pragma("unroll")                                              \
                for (int nt = 0; nt < 4; nt++) {                               \
                    uint32_t bp[4];                                            \
                    uint32_t off = (uint32_t)((kh * 32 + g * 8 + lr) * LDA + wc * 32 + nt * 8) * 2; \
                    LDM_X4T(bp[0], bp[1], bp[2], bp[3], pBq + off);            \
                    _Pragma("unroll")                                          \
                    for (int k2 = 0; k2 < 2; k2++) {                           \
                        int ks = kh * 2 + k2;                                  \
                        mma_f16(agg[nt], ahh + 4*ks, bp[2*k2], bp[2*k2+1]);    \
                    }                                                          \
                }                                                              \
            }                                                                  \
        }

        // stage 0: mma1 e0,e1 -> P0 (X tile), P1
        DO_MMA1(Wt[0], Pt01[0])
        DO_MMA1(Wt[1], Pt01[1])
        __syncthreads();                        // sync 3: P0/P1 ready

        // stage 1: mma2 e0,e1 (reads P0/P1, H0/H1) + mma1 e2,e3 -> P2/P3 (dead W0/W1)
        DO_MMA2(Ht[0], Pt01[0])
        DO_MMA1(Wt[2], Pt23[0])
        DO_MMA2(Ht[1], Pt01[1])
        DO_MMA1(Wt[3], Pt23[1])
        __syncthreads();                        // sync 4: P2/P3 ready

        // stage 2: mma2 e2,e3 + node-lin (NW tile resident since burst)
        DO_MMA2(Ht[2], Pt23[0])
        DO_MMA2(Ht[3], Pt23[1])
        if (eg == 0) {
            uint32_t wB = smem_u32(NWt);
#pragma unroll
            for (int kh = 0; kh < 2; kh++) {
#pragma unroll
                for (int nt = 0; nt < 4; nt++) {
                    uint32_t bw[4];
                    uint32_t off = (uint32_t)((kh * 32 + g * 8 + lr) * LDA + wc * 32 + nt * 8) * 2;
                    LDM_X4T(bw[0], bw[1], bw[2], bw[3], wB + off);
#pragma unroll
                    for (int k2 = 0; k2 < 2; k2++) {
                        int ks = kh * 2 + k2;
                        mma_f16(agg[nt], xh + 4*ks, bw[2*k2], bw[2*k2+1]);
                    }
                }
            }
        }
#undef DO_MMA1
#undef DO_MMA2

        // ---- store partial ----
        float* Cdst = g_part[eg] + bt * (Nn * FOUTn);
#pragma unroll
        for (int nt = 0; nt < 4; nt++) {
            int col = wc * 32 + nt * 8 + cc2;
            *(float2*)(Cdst + (wr * 16 + cr) * FOUTn + col)     = make_float2(agg[nt][0], agg[nt][1]);
            *(float2*)(Cdst + (wr * 16 + cr + 8) * FOUTn + col) = make_float2(agg[nt][2], agg[nt][3]);
        }

        // ---- per-bt finisher: last of 4 eg-blocks sums + gelu + out ----
        __threadfence();
        __syncthreads();
        if (tid == 0) s_old = atomicAdd(&g_btcnt[bt], 1u);
        __syncthreads();
        if (s_old == 3u) {
            __threadfence();
            int base = bt * (Nn * FOUTn);
#pragma unroll
            for (int l = 0; l < 4; l++) {
                int idx = tid + l * 256;          // 1024 float4 tasks for this bt
                int e0 = base + idx * 4;
                int o  = (idx * 4) & 63;
                float4 p0 = *(const float4*)(g_part[0] + e0);
                float4 p1 = *(const float4*)(g_part[1] + e0);
                float4 p2 = *(const float4*)(g_part[2] + e0);
                float4 p3 = *(const float4*)(g_part[3] + e0);
                float4 nbv = *(const float4*)(nb + o);
                float4 t2v = *(const float4*)(g_T2 + bt * FOUTn + o);
                float v0 = p0.x + p1.x + p2.x + p3.x + nbv.x + t2v.x;
                float v1 = p0.y + p1.y + p2.y + p3.y + nbv.y + t2v.y;
                float v2 = p0.z + p1.z + p2.z + p3.z + nbv.z + t2v.z;
                float v3 = p0.w + p1.w + p2.w + p3.w + nbv.w + t2v.w;
                *(float4*)(out + e0) = make_float4(gelu_exact(v0), gelu_exact(v1),
                                                   gelu_exact(v2), gelu_exact(v3));
            }
            if (tid == 0) g_btcnt[bt] = 0;        // reset for next graph replay
        }
    }
}

extern "C" void kernel_launch(void* const* d_in, const int* in_sizes, int n_in,
                              void* d_out, int out_size) {
    const float* x   = (const float*)d_in[0];
    const float* adj = (const float*)d_in[1];
    const float* ew1 = (const float*)d_in[2];
    const float* eb1 = (const float*)d_in[3];
    const float* ew2 = (const float*)d_in[4];
    const float* eb2 = (const float*)d_in[5];
    const float* nw  = (const float*)d_in[6];
    const float* nb  = (const float*)d_in[7];
    const float* gw  = (const float*)d_in[8];
    const float* gb  = (const float*)d_in[9];
    const float* gms = (const float*)d_in[10];
    float* out = (float*)d_out;

    cudaFuncSetAttribute(k_all, cudaFuncAttributeMaxDynamicSharedMemorySize, FUS_SMEM);
    k_all<<<NBLK, 256, FUS_SMEM>>>(x, adj, ew1, eb1, ew2, eb2, nw, nb, gw, gb, gms, out);
}